// round 3
// baseline (speedup 1.0000x reference)
#include <cuda_runtime.h>
#include <stdint.h>

// Problem shape (fixed by the dataset)
#define NB 8
#define NN 4096
#define DD 512

// Tiling
#define BM 128
#define BN_T 128
#define BK 16
#define NKT (DD / BK)   // 32

// Scratch: per-row squared norms (no cudaMalloc allowed)
__device__ float g_sq[NB * NN];

__device__ __forceinline__ uint32_t f2tf32(float f) {
    uint32_t u;
    asm("cvt.rna.tf32.f32 %0, %1;" : "=r"(u) : "f"(f));
    return u;
}

__device__ __forceinline__ void mma_tf32(float c[4], const uint32_t a[4], const uint32_t b[2]) {
    asm volatile(
        "mma.sync.aligned.m16n8k8.row.col.f32.tf32.tf32.f32 "
        "{%0,%1,%2,%3}, {%4,%5,%6,%7}, {%8,%9}, {%0,%1,%2,%3};\n"
        : "+f"(c[0]), "+f"(c[1]), "+f"(c[2]), "+f"(c[3])
        : "r"(a[0]), "r"(a[1]), "r"(a[2]), "r"(a[3]),
          "r"(b[0]), "r"(b[1]));
}

// ---------------------------------------------------------------------------
// Kernel 1: sq[b*N + i] = sum_d x[b,i,d]^2   (one warp per row)
// ---------------------------------------------------------------------------
__global__ void sq_kernel(const float* __restrict__ x) {
    int row  = blockIdx.x * 8 + (threadIdx.x >> 5);   // 8 warps / block
    int lane = threadIdx.x & 31;
    const float4* p = reinterpret_cast<const float4*>(x + (size_t)row * DD);
    float s = 0.0f;
#pragma unroll
    for (int i = 0; i < 4; ++i) {
        float4 v = p[lane + i * 32];
        s += v.x * v.x + v.y * v.y + v.z * v.z + v.w * v.w;
    }
#pragma unroll
    for (int o = 16; o > 0; o >>= 1) s += __shfl_xor_sync(0xffffffffu, s, o);
    if (lane == 0) g_sq[row] = s;
}

// ---------------------------------------------------------------------------
// Kernel 2: tiled TF32 mma.sync Gram + fused hyperbolic-distance epilogue.
//   out[b,i,j] = acosh(1 + 2*||xi-xj|| / ((1-||xi||^2)(1-||xj||^2))), diag 0
// Block = 128x128 output tile, 256 threads (8 warps, 4x2, each 32x64).
// ---------------------------------------------------------------------------
__global__ __launch_bounds__(256) void hyp_kernel(const float* __restrict__ X,
                                                  float* __restrict__ out) {
    // tf32 operand tiles, double-buffered; row stride 20 (pad 4) = conflict-free
    __shared__ uint32_t As[2][BM][20];
    __shared__ uint32_t Bs[2][BN_T][20];
    __shared__ float sqRow[BM], sqCol[BN_T], invRow[BM], invCol[BN_T];

    const int b       = blockIdx.z;
    const int rowBase = blockIdx.y * BM;
    const int colBase = blockIdx.x * BN_T;
    const int tid     = threadIdx.x;
    const int lane    = tid & 31;
    const int wid     = tid >> 5;
    const int wr      = (wid & 3) * 32;   // warp row origin in tile
    const int wc      = (wid >> 2) * 64;  // warp col origin in tile
    const int gr      = lane >> 2;        // groupID  (0..7)
    const int gq      = lane & 3;         // thread-in-group (0..3)

    const float* Xb = X + (size_t)b * NN * DD;
    const float* Ag = Xb + (size_t)rowBase * DD;
    const float* Bg = Xb + (size_t)colBase * DD;

    // Stage sq / 1/(1-sq) for this tile's rows and cols
    if (tid < BM) {
        float s = g_sq[b * NN + rowBase + tid];
        sqRow[tid] = s;
        invRow[tid] = 1.0f / (1.0f - s);
    } else {
        int t = tid - BM;
        float s = g_sq[b * NN + colBase + t];
        sqCol[t] = s;
        invCol[t] = 1.0f / (1.0f - s);
    }

    const int lrow = tid >> 2;  // 0..63
    const int lc4  = tid & 3;   // 0..3 (float4 column)

    // Prologue: load k-tile 0 into buffer 0
#pragma unroll
    for (int i = 0; i < 2; ++i) {
        int row = lrow + i * 64;
        float4 va = *reinterpret_cast<const float4*>(Ag + (size_t)row * DD + lc4 * 4);
        float4 vb = *reinterpret_cast<const float4*>(Bg + (size_t)row * DD + lc4 * 4);
        uint4 ua = make_uint4(f2tf32(va.x), f2tf32(va.y), f2tf32(va.z), f2tf32(va.w));
        uint4 ub = make_uint4(f2tf32(vb.x), f2tf32(vb.y), f2tf32(vb.z), f2tf32(vb.w));
        *reinterpret_cast<uint4*>(&As[0][row][lc4 * 4]) = ua;
        *reinterpret_cast<uint4*>(&Bs[0][row][lc4 * 4]) = ub;
    }
    __syncthreads();

    float c[2][8][4];
#pragma unroll
    for (int mi = 0; mi < 2; ++mi)
#pragma unroll
        for (int ni = 0; ni < 8; ++ni)
#pragma unroll
            for (int t = 0; t < 4; ++t) c[mi][ni][t] = 0.0f;

    float4 pa[2], pb[2];

    for (int kt = 0; kt < NKT; ++kt) {
        const int cur = kt & 1;

        // Prefetch next k-tile global -> registers
        if (kt + 1 < NKT) {
            const int koff = (kt + 1) * BK;
#pragma unroll
            for (int i = 0; i < 2; ++i) {
                int row = lrow + i * 64;
                pa[i] = *reinterpret_cast<const float4*>(Ag + (size_t)row * DD + koff + lc4 * 4);
                pb[i] = *reinterpret_cast<const float4*>(Bg + (size_t)row * DD + koff + lc4 * 4);
            }
        }

        // Compute on current buffer: 2 k-steps of 8
#pragma unroll
        for (int ks = 0; ks < 2; ++ks) {
            const int k0 = ks * 8;
            uint32_t a[2][4];
#pragma unroll
            for (int mi = 0; mi < 2; ++mi) {
                int row = wr + mi * 16 + gr;
                a[mi][0] = As[cur][row][k0 + gq];
                a[mi][1] = As[cur][row + 8][k0 + gq];
                a[mi][2] = As[cur][row][k0 + gq + 4];
                a[mi][3] = As[cur][row + 8][k0 + gq + 4];
            }
            uint32_t bb[8][2];
#pragma unroll
            for (int ni = 0; ni < 8; ++ni) {
                int col = wc + ni * 8 + gr;
                bb[ni][0] = Bs[cur][col][k0 + gq];
                bb[ni][1] = Bs[cur][col][k0 + gq + 4];
            }
#pragma unroll
            for (int mi = 0; mi < 2; ++mi)
#pragma unroll
                for (int ni = 0; ni < 8; ++ni)
                    mma_tf32(c[mi][ni], a[mi], bb[ni]);
        }

        // Store prefetched tile into the other buffer
        if (kt + 1 < NKT) {
            const int nxt = cur ^ 1;
#pragma unroll
            for (int i = 0; i < 2; ++i) {
                int row = lrow + i * 64;
                uint4 ua = make_uint4(f2tf32(pa[i].x), f2tf32(pa[i].y), f2tf32(pa[i].z), f2tf32(pa[i].w));
                uint4 ub = make_uint4(f2tf32(pb[i].x), f2tf32(pb[i].y), f2tf32(pb[i].z), f2tf32(pb[i].w));
                *reinterpret_cast<uint4*>(&As[nxt][row][lc4 * 4]) = ua;
                *reinterpret_cast<uint4*>(&Bs[nxt][row][lc4 * 4]) = ub;
            }
            __syncthreads();
        }
    }

    // Fused epilogue: gram -> hyperbolic distance, diagonal forced to 0.
#pragma unroll
    for (int mi = 0; mi < 2; ++mi) {
#pragma unroll
        for (int half = 0; half < 2; ++half) {
            const int lr   = wr + mi * 16 + gr + half * 8;
            const int grow = rowBase + lr;
            const float si  = sqRow[lr];
            const float ivi = invRow[lr];
            float* orow = out + ((size_t)b * NN + grow) * NN + colBase;
#pragma unroll
            for (int ni = 0; ni < 8; ++ni) {
                const int lcol = wc + ni * 8 + 2 * gq;
                const float g0 = c[mi][ni][half * 2 + 0];
                const float g1 = c[mi][ni][half * 2 + 1];
                const float sj0 = sqCol[lcol], sj1 = sqCol[lcol + 1];
                float d20 = fmaxf(si + sj0 - 2.0f * g0, 0.0f);
                float d21 = fmaxf(si + sj1 - 2.0f * g1, 0.0f);
                float dn0 = sqrtf(d20);
                float dn1 = sqrtf(d21);
                float arg0 = fmaf(dn0, 2.0f * ivi * invCol[lcol], 1.0f);
                float arg1 = fmaf(dn1, 2.0f * ivi * invCol[lcol + 1], 1.0f);
                float dist0 = (arg0 > 1.0f) ? __logf(arg0 + sqrtf(arg0 * arg0 - 1.0f)) : 0.0f;
                float dist1 = (arg1 > 1.0f) ? __logf(arg1 + sqrtf(arg1 * arg1 - 1.0f)) : 0.0f;
                if (grow == colBase + lcol) dist0 = 0.0f;
                if (grow == colBase + lcol + 1) dist1 = 0.0f;
                *reinterpret_cast<float2*>(orow + lcol) = make_float2(dist0, dist1);
            }
        }
    }
}

extern "C" void kernel_launch(void* const* d_in, const int* in_sizes, int n_in,
                              void* d_out, int out_size) {
    const float* x = (const float*)d_in[0];
    float* out = (float*)d_out;

    // 1) per-row squared norms
    sq_kernel<<<(NB * NN) / 8, 256>>>(x);

    // 2) tiled gram + fused hyperbolic epilogue
    dim3 grid(NN / BN_T, NN / BM, NB);
    hyp_kernel<<<grid, 256>>>(x, out);
}

// round 5
// speedup vs baseline: 2.4200x; 2.4200x over previous
#include <cuda_runtime.h>
#include <stdint.h>

#define NB 8
#define NN 4096
#define DD 512
#define NT 16              // 4096/256... tiles per dim at BM=128 -> 32? no: 4096/128 = 32
// NOTE: BM=BN=128 -> 32 tiles/dim; triangle = 32*33/2 = 528 tiles/batch
#define TPD 32             // tiles per dimension
#define NTILES 528         // TPD*(TPD+1)/2

#define BM 128
#define BN 128
#define BK 16
#define NKT (DD / BK)      // 32
#define STAGES 4
#define THREADS 256

#define STAGE_BYTES 20480  // A 10240 + B 10240 (128 rows x 80B)
#define TS 132             // epilogue tile stride in words
#define SQROW_OFF  81920
#define INVROW_OFF 82432
#define SQCOL_OFF  82944
#define INVCOL_OFF 83456
#define SMEM_TOTAL 83968

__device__ float g_sq[NB * NN];

static __device__ __forceinline__ uint32_t smem_u32(const void* p) {
    uint32_t a;
    asm("{ .reg .u64 t; cvta.to.shared.u64 t, %1; cvt.u32.u64 %0, t; }" : "=r"(a) : "l"(p));
    return a;
}

#define CP16(dst, src) \
    asm volatile("cp.async.cg.shared.global [%0], [%1], 16;" :: "r"(dst), "l"(src))
#define CP_COMMIT() asm volatile("cp.async.commit_group;" ::: "memory")
#define CP_WAIT(n)  asm volatile("cp.async.wait_group %0;" :: "n"(n) : "memory")

static __device__ __forceinline__ void ldsm4(uint32_t r[4], uint32_t addr) {
    asm volatile("ldmatrix.sync.aligned.m8n8.x4.shared.b16 {%0,%1,%2,%3}, [%4];"
                 : "=r"(r[0]), "=r"(r[1]), "=r"(r[2]), "=r"(r[3]) : "r"(addr));
}

static __device__ __forceinline__ void mma_tf32(float c[4], const uint32_t a[4],
                                                const uint32_t b0, const uint32_t b1) {
    asm volatile(
        "mma.sync.aligned.m16n8k8.row.col.f32.tf32.tf32.f32 "
        "{%0,%1,%2,%3}, {%4,%5,%6,%7}, {%8,%9}, {%0,%1,%2,%3};\n"
        : "+f"(c[0]), "+f"(c[1]), "+f"(c[2]), "+f"(c[3])
        : "r"(a[0]), "r"(a[1]), "r"(a[2]), "r"(a[3]), "r"(b0), "r"(b1));
}

// ---------------------------------------------------------------------------
// Kernel 1: per-row squared norms
// ---------------------------------------------------------------------------
__global__ void sq_kernel(const float* __restrict__ x) {
    int row  = blockIdx.x * 8 + (threadIdx.x >> 5);
    int lane = threadIdx.x & 31;
    const float4* p = reinterpret_cast<const float4*>(x + (size_t)row * DD);
    float s = 0.0f;
#pragma unroll
    for (int i = 0; i < 4; ++i) {
        float4 v = p[lane + i * 32];
        s += v.x * v.x + v.y * v.y + v.z * v.z + v.w * v.w;
    }
#pragma unroll
    for (int o = 16; o > 0; o >>= 1) s += __shfl_xor_sync(0xffffffffu, s, o);
    if (lane == 0) g_sq[row] = s;
}

// ---------------------------------------------------------------------------
// Kernel 2: symmetric (upper-triangle) tf32 mma.sync Gram + hyperbolic epilogue
// 128x128 tile, 256 threads (8 warps 4x2, each 32x64), ldmatrix fragments,
// cp.async 4-stage pipeline, smem-staged transpose for the mirror tile.
// ---------------------------------------------------------------------------
__global__ __launch_bounds__(THREADS, 2) void hyp_sym(const float* __restrict__ X,
                                                      float* __restrict__ out) {
    extern __shared__ __align__(1024) char smem[];
    const uint32_t sbase = smem_u32(smem);
    float* tileS = reinterpret_cast<float*>(smem);
    float* sqRowS  = reinterpret_cast<float*>(smem + SQROW_OFF);
    float* invRowS = reinterpret_cast<float*>(smem + INVROW_OFF);
    float* sqColS  = reinterpret_cast<float*>(smem + SQCOL_OFF);
    float* invColS = reinterpret_cast<float*>(smem + INVCOL_OFF);

    const int b = blockIdx.z;
    // decode upper-triangle tile index -> (tr, tc), tr <= tc
    int t = blockIdx.x, tr = 0;
    while (t >= TPD - tr) { t -= TPD - tr; ++tr; }
    const int tc = tr + t;
    const int rowBase = tr * BM;
    const int colBase = tc * BN;

    const int tid  = threadIdx.x;
    const int lane = tid & 31;
    const int wid  = tid >> 5;
    const int wr   = (wid & 3) * 32;
    const int wc   = (wid >> 2) * 64;
    const int gr   = lane >> 2;
    const int gq   = lane & 3;

    const float* Xb = X + (size_t)b * NN * DD;

    // ---- cp.async source/dst geometry: 4 x 16B per thread per stage ----
    const int rowL = tid >> 2;          // 0..63
    const int seg  = tid & 3;           // 16B segment (BK=16 floats = 4 segs)
    const float* pA0 = Xb + (size_t)(rowBase + rowL) * DD + seg * 4;
    const float* pA1 = pA0 + (size_t)64 * DD;
    const float* pB0 = Xb + (size_t)(colBase + rowL) * DD + seg * 4;
    const float* pB1 = pB0 + (size_t)64 * DD;
    const uint32_t dOffA0 = (uint32_t)rowL * 80 + seg * 16;
    const uint32_t dOffA1 = dOffA0 + 64 * 80;

#define LOAD_TILE(g, s)                                                \
    do {                                                               \
        uint32_t sb = sbase + (uint32_t)(s) * STAGE_BYTES;             \
        CP16(sb + dOffA0,         pA0 + (size_t)(g) * BK);             \
        CP16(sb + dOffA1,         pA1 + (size_t)(g) * BK);             \
        CP16(sb + 10240 + dOffA0, pB0 + (size_t)(g) * BK);             \
        CP16(sb + 10240 + dOffA1, pB1 + (size_t)(g) * BK);             \
    } while (0)

    // ---- ldmatrix per-lane address offsets (bytes within a stage) ----
    const int q = lane >> 3;
    uint32_t offA[2], offB[4];
#pragma unroll
    for (int mi = 0; mi < 2; ++mi) {
        int r = wr + mi * 16 + (lane & 7) + (q & 1) * 8;
        offA[mi] = (uint32_t)r * 80 + (uint32_t)(lane >> 4) * 16;
    }
#pragma unroll
    for (int p = 0; p < 4; ++p) {
        int col = wc + (2 * p + (lane >> 4)) * 8 + (lane & 7);
        offB[p] = (uint32_t)col * 80 + (uint32_t)(q & 1) * 16;
    }

    // stage sq / 1/(1-sq)
    if (tid < BM) {
        float s = g_sq[b * NN + rowBase + tid];
        sqRowS[tid] = s; invRowS[tid] = 1.0f / (1.0f - s);
    } else {
        int u = tid - BM;
        float s = g_sq[b * NN + colBase + u];
        sqColS[u] = s; invColS[u] = 1.0f / (1.0f - s);
    }

    // prologue: k-tiles 0..2 into stages 0..2
    LOAD_TILE(0, 0); CP_COMMIT();
    LOAD_TILE(1, 1); CP_COMMIT();
    LOAD_TILE(2, 2); CP_COMMIT();

    float c[2][8][4];
#pragma unroll
    for (int mi = 0; mi < 2; ++mi)
#pragma unroll
        for (int ni = 0; ni < 8; ++ni)
#pragma unroll
            for (int v = 0; v < 4; ++v) c[mi][ni][v] = 0.0f;

    for (int kt = 0; kt < NKT; ++kt) {
        CP_WAIT(2);            // k-tile kt resident
        __syncthreads();       // all warps done with compute(kt-1); stage (kt-1)%4 free
        if (kt + 3 < NKT) LOAD_TILE(kt + 3, (kt + 3) & 3);
        CP_COMMIT();           // commit every iter (possibly empty) to keep wait math simple

        const uint32_t aSt = sbase + (uint32_t)(kt & 3) * STAGE_BYTES;
        const uint32_t bSt = aSt + 10240;
#pragma unroll
        for (int ks = 0; ks < 2; ++ks) {
            uint32_t a[2][4], bb[4][4];
            ldsm4(a[0], aSt + offA[0] + ks * 32);
            ldsm4(a[1], aSt + offA[1] + ks * 32);
#pragma unroll
            for (int p = 0; p < 4; ++p) ldsm4(bb[p], bSt + offB[p] + ks * 32);
#pragma unroll
            for (int mi = 0; mi < 2; ++mi)
#pragma unroll
                for (int p = 0; p < 4; ++p) {
                    mma_tf32(c[mi][2 * p + 0], a[mi], bb[p][0], bb[p][1]);
                    mma_tf32(c[mi][2 * p + 1], a[mi], bb[p][2], bb[p][3]);
                }
        }
    }
    __syncthreads();   // mainloop fully done before tile staging overwrites stage smem

    // ---- epilogue: distances -> smem tile ----
#pragma unroll
    for (int mi = 0; mi < 2; ++mi) {
#pragma unroll
        for (int half = 0; half < 2; ++half) {
            const int lr = wr + mi * 16 + gr + half * 8;
            const int grow = rowBase + lr;
            const float si  = sqRowS[lr];
            const float tiv = 2.0f * invRowS[lr];
#pragma unroll
            for (int ni = 0; ni < 8; ++ni) {
                const int lcol = wc + ni * 8 + 2 * gq;
                const float g0 = c[mi][ni][half * 2 + 0];
                const float g1 = c[mi][ni][half * 2 + 1];
                float d20 = fmaxf(si + sqColS[lcol]     - 2.0f * g0, 0.0f);
                float d21 = fmaxf(si + sqColS[lcol + 1] - 2.0f * g1, 0.0f);
                float arg0 = fmaf(sqrtf(d20), tiv * invColS[lcol],     1.0f);
                float arg1 = fmaf(sqrtf(d21), tiv * invColS[lcol + 1], 1.0f);
                float dist0 = (arg0 > 1.0f) ? __logf(arg0 + sqrtf(arg0 * arg0 - 1.0f)) : 0.0f;
                float dist1 = (arg1 > 1.0f) ? __logf(arg1 + sqrtf(arg1 * arg1 - 1.0f)) : 0.0f;
                if (grow == colBase + lcol)     dist0 = 0.0f;
                if (grow == colBase + lcol + 1) dist1 = 0.0f;
                *reinterpret_cast<float2*>(tileS + lr * TS + lcol) = make_float2(dist0, dist1);
            }
        }
    }
    __syncthreads();

    // ---- direct write (coalesced float4 rows) ----
    {
        const int l4 = tid & 31;
        const int rw = tid >> 5;
#pragma unroll
        for (int i = 0; i < 16; ++i) {
            int r = rw + i * 8;
            float4 v = *reinterpret_cast<const float4*>(tileS + r * TS + l4 * 4);
            *reinterpret_cast<float4*>(out + ((size_t)b * NN + rowBase + r) * NN + colBase + l4 * 4) = v;
        }
    }
    // ---- mirror write (transpose read from smem, coalesced 4B stores) ----
    if (tr != tc) {
        const int w = tid >> 5;
#pragma unroll
        for (int i = 0; i < 16; ++i) {
            int cc = w + i * 8;
            float* mrow = out + ((size_t)b * NN + colBase + cc) * NN + rowBase;
#pragma unroll
            for (int j = 0; j < 4; ++j)
                mrow[lane + 32 * j] = tileS[(lane + 32 * j) * TS + cc];
        }
    }
}

extern "C" void kernel_launch(void* const* d_in, const int* in_sizes, int n_in,
                              void* d_out, int out_size) {
    const float* x = (const float*)d_in[0];
    float* out = (float*)d_out;

    cudaFuncSetAttribute(hyp_sym, cudaFuncAttributeMaxDynamicSharedMemorySize, SMEM_TOTAL);

    sq_kernel<<<(NB * NN) / 8, 256>>>(x);

    dim3 grid(NTILES, 1, NB);   // 528 upper-triangle tiles x 8 batches
    hyp_sym<<<grid, THREADS, SMEM_TOTAL>>>(x, out);
}